// round 1
// baseline (speedup 1.0000x reference)
#include <cuda_runtime.h>
#include <math.h>

// Problem constants
constexpr int B_ = 16;
constexpr int N_ = 4096;
constexpr int D_ = 256;
constexpr float EPS_ = 1e-6f;
constexpr int SPLITK = 4;

// -------- scratch (device globals; no allocation allowed) --------
__device__ float g_phi_q[(size_t)B_ * N_ * D_];   // 64 MB
__device__ float g_phi_k[(size_t)B_ * N_ * D_];   // 64 MB
__device__ float g_Vb  [(size_t)B_ * N_ * D_];    // 64 MB
__device__ float g_KVp [(size_t)SPLITK * B_ * D_ * D_]; // 16 MB split-K partials
__device__ float g_KV  [(size_t)B_ * D_ * D_];    // 4 MB
__device__ float g_rowscale[B_ * N_];             // sigmoid(rs)/(rs+eps)

__device__ __forceinline__ float sigmoidf_(float x) { return 1.f / (1.f + expf(-x)); }

// ============================================================================
// Kernel 1: phi = sigmoid(X @ W + b), X = Q or K flattened to [B*N, D]
// 64x64x16 tiling, 256 threads, 4x4 microtile. blockIdx.z selects q/k.
// ============================================================================
__global__ void phi_gemm_kernel(const float* __restrict__ Q,
                                const float* __restrict__ Kin,
                                const float* __restrict__ Wq,
                                const float* __restrict__ bq,
                                const float* __restrict__ Wk,
                                const float* __restrict__ bk)
{
    const bool is_k = (blockIdx.z != 0);
    const float* A  = is_k ? Kin : Q;
    const float* W  = is_k ? Wk  : Wq;
    const float* bv = is_k ? bk  : bq;
    float* C        = is_k ? g_phi_k : g_phi_q;

    const int m0 = blockIdx.x * 64;   // over B*N = 65536
    const int n0 = blockIdx.y * 64;   // over D = 256

    __shared__ float As[16][64];      // [k][m]
    __shared__ float Bs[16][64];      // [k][n]

    const int tid = threadIdx.x;      // 256 threads
    const int tm = tid & 15, tn = tid >> 4;
    const int lr = tid >> 2, lk = (tid & 3) << 2;   // A-tile load: row, k4
    const int wr = tid >> 4, wc = (tid & 15) << 2;  // W-tile load: k, col4

    float acc[4][4] = {};

    for (int k0 = 0; k0 < D_; k0 += 16) {
        float4 a = *(const float4*)&A[(size_t)(m0 + lr) * D_ + k0 + lk];
        As[lk + 0][lr] = a.x; As[lk + 1][lr] = a.y;
        As[lk + 2][lr] = a.z; As[lk + 3][lr] = a.w;
        *(float4*)&Bs[wr][wc] = *(const float4*)&W[(size_t)(k0 + wr) * D_ + n0 + wc];
        __syncthreads();
#pragma unroll
        for (int k = 0; k < 16; k++) {
            float4 av = *(const float4*)&As[k][tm << 2];
            float4 bw = *(const float4*)&Bs[k][tn << 2];
            float a4[4] = {av.x, av.y, av.z, av.w};
            float b4[4] = {bw.x, bw.y, bw.z, bw.w};
#pragma unroll
            for (int i = 0; i < 4; i++)
#pragma unroll
                for (int j = 0; j < 4; j++)
                    acc[i][j] = fmaf(a4[i], b4[j], acc[i][j]);
        }
        __syncthreads();
    }

#pragma unroll
    for (int i = 0; i < 4; i++) {
        const int row = m0 + (tm << 2) + i;
        const int col = n0 + (tn << 2);
        float4 o;
        o.x = sigmoidf_(acc[i][0] + bv[col + 0]);
        o.y = sigmoidf_(acc[i][1] + bv[col + 1]);
        o.z = sigmoidf_(acc[i][2] + bv[col + 2]);
        o.w = sigmoidf_(acc[i][3] + bv[col + 3]);
        *(float4*)&C[(size_t)row * D_ + col] = o;
    }
}

// ============================================================================
// Kernel 2: rowscale[b,n] = sigmoid(rs)/(rs+eps), rs = sum_d phi_q[b,n,d]
// One warp per row, 8 rows per block.
// ============================================================================
__global__ void rowscale_kernel()
{
    const int row  = blockIdx.x * 8 + (threadIdx.x >> 5);  // in [0, B*N)
    const int lane = threadIdx.x & 31;
    const float* p = g_phi_q + (size_t)row * D_;
    float s = 0.f;
#pragma unroll
    for (int i = lane; i < D_; i += 32) s += p[i];
#pragma unroll
    for (int off = 16; off; off >>= 1) s += __shfl_xor_sync(0xffffffffu, s, off);
    if (lane == 0) g_rowscale[row] = sigmoidf_(s) / (s + EPS_);
}

// ============================================================================
// Kernel 3: column softmax over N of x[b,n,d] = phi_k*V / (colsum_n phi_k + eps)
// One block owns (b, 16 columns) for ALL n -> no global sync needed.
// 256 threads = 16 n-lanes x 16 d-lanes. Three streaming passes.
// ============================================================================
__global__ void col_softmax_kernel(const float* __restrict__ V)
{
    const int b  = blockIdx.x;
    const int td = threadIdx.x & 15;
    const int tn = threadIdx.x >> 4;           // 16 n-lanes
    const int d  = blockIdx.y * 16 + td;

    const float* Pk = g_phi_k + (size_t)b * N_ * D_ + d;
    const float* Vv = V       + (size_t)b * N_ * D_ + d;
    float*       Vb = g_Vb    + (size_t)b * N_ * D_ + d;

    __shared__ float s1[16][17], s2[16][17];

    // pass 1: colsum(phi_k) and max(phi_k*V)
    float csum = 0.f, ymax = -1e30f;
    for (int n = tn; n < N_; n += 16) {
        float pk = Pk[(size_t)n * D_];
        float y  = pk * Vv[(size_t)n * D_];
        csum += pk;
        ymax = fmaxf(ymax, y);
    }
    s1[tn][td] = csum; s2[tn][td] = ymax;
    __syncthreads();
    for (int h = 8; h; h >>= 1) {
        if (tn < h) {
            s1[tn][td] += s1[tn + h][td];
            s2[tn][td] = fmaxf(s2[tn][td], s2[tn + h][td]);
        }
        __syncthreads();
    }
    const float c    = 1.f / (s1[0][td] + EPS_);  // scaling > 0, so max(c*y)=c*max(y)
    const float xmax = c * s2[0][td];
    __syncthreads();

    // pass 2: sum of exp(x - xmax)
    float se = 0.f;
    for (int n = tn; n < N_; n += 16) {
        float x = c * Pk[(size_t)n * D_] * Vv[(size_t)n * D_];
        se += expf(x - xmax);
    }
    s1[tn][td] = se;
    __syncthreads();
    for (int h = 8; h; h >>= 1) {
        if (tn < h) s1[tn][td] += s1[tn + h][td];
        __syncthreads();
    }
    const float inv = 1.f / s1[0][td];

    // pass 3: write V_b
    for (int n = tn; n < N_; n += 16) {
        float x = c * Pk[(size_t)n * D_] * Vv[(size_t)n * D_];
        Vb[(size_t)n * D_] = expf(x - xmax) * inv;
    }
}

// ============================================================================
// Kernel 4: KV partials = phi_k^T @ V_b per batch, split-K over N (determin.)
// C tile 64x64, K-chunk 16. Both operand tiles load k-major (fully coalesced).
// grid (D/64, D/64, B*SPLITK)
// ============================================================================
__global__ void kv_gemm_kernel()
{
    const int b  = blockIdx.z / SPLITK;
    const int s  = blockIdx.z % SPLITK;
    const int d0 = blockIdx.x * 64;
    const int e0 = blockIdx.y * 64;

    const float* Pk = g_phi_k + (size_t)b * N_ * D_;
    const float* Vb = g_Vb    + (size_t)b * N_ * D_;
    float* Cout = g_KVp + (size_t)s * B_ * D_ * D_ + (size_t)b * D_ * D_;

    const int tid = threadIdx.x;
    const int tm = tid & 15, tn = tid >> 4;
    const int nr = tid >> 4, dc = (tid & 15) << 2;

    __shared__ float As[16][64], Bs[16][64];
    float acc[4][4] = {};

    const int nbeg = s * (N_ / SPLITK);
    const int nend = nbeg + (N_ / SPLITK);
    for (int n0 = nbeg; n0 < nend; n0 += 16) {
        *(float4*)&As[nr][dc] = *(const float4*)&Pk[(size_t)(n0 + nr) * D_ + d0 + dc];
        *(float4*)&Bs[nr][dc] = *(const float4*)&Vb[(size_t)(n0 + nr) * D_ + e0 + dc];
        __syncthreads();
#pragma unroll
        for (int k = 0; k < 16; k++) {
            float4 av = *(const float4*)&As[k][tm << 2];
            float4 bw = *(const float4*)&Bs[k][tn << 2];
            float a4[4] = {av.x, av.y, av.z, av.w};
            float b4[4] = {bw.x, bw.y, bw.z, bw.w};
#pragma unroll
            for (int i = 0; i < 4; i++)
#pragma unroll
                for (int j = 0; j < 4; j++)
                    acc[i][j] = fmaf(a4[i], b4[j], acc[i][j]);
        }
        __syncthreads();
    }

#pragma unroll
    for (int i = 0; i < 4; i++) {
        const int dd = d0 + (tm << 2) + i;
        *(float4*)&Cout[(size_t)dd * D_ + e0 + (tn << 2)] =
            make_float4(acc[i][0], acc[i][1], acc[i][2], acc[i][3]);
    }
}

// Deterministic split-K reduction
__global__ void kv_reduce_kernel()
{
    const size_t i = (size_t)blockIdx.x * 256 + threadIdx.x;
    const size_t stride = (size_t)B_ * D_ * D_;
    float s = 0.f;
#pragma unroll
    for (int p = 0; p < SPLITK; p++) s += g_KVp[p * stride + i];
    g_KV[i] = s;
}

// ============================================================================
// Kernel 5: out[b,n,e] = rowscale[b,n] * sum_d phi_q[b,n,d] * KV[b,d,e]
// grid (N/64, D/64, B)
// ============================================================================
__global__ void out_gemm_kernel(float* __restrict__ out)
{
    const int b  = blockIdx.z;
    const int m0 = blockIdx.x * 64;   // n within batch
    const int e0 = blockIdx.y * 64;

    const float* Aq = g_phi_q + (size_t)b * N_ * D_;
    const float* KV = g_KV    + (size_t)b * D_ * D_;

    const int tid = threadIdx.x;
    const int tm = tid & 15, tn = tid >> 4;
    const int lr = tid >> 2, lk = (tid & 3) << 2;
    const int wr = tid >> 4, wc = (tid & 15) << 2;

    __shared__ float As[16][64], Bs[16][64];
    float acc[4][4] = {};

    for (int k0 = 0; k0 < D_; k0 += 16) {
        float4 a = *(const float4*)&Aq[(size_t)(m0 + lr) * D_ + k0 + lk];
        As[lk + 0][lr] = a.x; As[lk + 1][lr] = a.y;
        As[lk + 2][lr] = a.z; As[lk + 3][lr] = a.w;
        *(float4*)&Bs[wr][wc] = *(const float4*)&KV[(size_t)(k0 + wr) * D_ + e0 + wc];
        __syncthreads();
#pragma unroll
        for (int k = 0; k < 16; k++) {
            float4 av = *(const float4*)&As[k][tm << 2];
            float4 bw = *(const float4*)&Bs[k][tn << 2];
            float a4[4] = {av.x, av.y, av.z, av.w};
            float b4[4] = {bw.x, bw.y, bw.z, bw.w};
#pragma unroll
            for (int i = 0; i < 4; i++)
#pragma unroll
                for (int j = 0; j < 4; j++)
                    acc[i][j] = fmaf(a4[i], b4[j], acc[i][j]);
        }
        __syncthreads();
    }

#pragma unroll
    for (int i = 0; i < 4; i++) {
        const int n  = m0 + (tm << 2) + i;
        const float sc = g_rowscale[b * N_ + n];
        *(float4*)&out[((size_t)b * N_ + n) * D_ + e0 + (tn << 2)] =
            make_float4(sc * acc[i][0], sc * acc[i][1],
                        sc * acc[i][2], sc * acc[i][3]);
    }
}

// ============================================================================
// Launch: inputs per metadata order: Q, K, V, Wq, bq, Wk, bk
// ============================================================================
extern "C" void kernel_launch(void* const* d_in, const int* in_sizes, int n_in,
                              void* d_out, int out_size)
{
    const float* Q  = (const float*)d_in[0];
    const float* K  = (const float*)d_in[1];
    const float* V  = (const float*)d_in[2];
    const float* Wq = (const float*)d_in[3];
    const float* bq = (const float*)d_in[4];
    const float* Wk = (const float*)d_in[5];
    const float* bk = (const float*)d_in[6];
    float* out = (float*)d_out;

    // 1. phi_q, phi_k (two fused-sigmoid GEMMs)
    phi_gemm_kernel<<<dim3((B_ * N_) / 64, D_ / 64, 2), 256>>>(Q, K, Wq, bq, Wk, bk);
    // 2. row scales from phi_q
    rowscale_kernel<<<(B_ * N_) / 8, 256>>>();
    // 3. column softmax -> V_b
    col_softmax_kernel<<<dim3(B_, D_ / 16), 256>>>(V);
    // 4. KV = phi_k^T @ V_b (split-K partials, then deterministic reduce)
    kv_gemm_kernel<<<dim3(D_ / 64, D_ / 64, B_ * SPLITK), 256>>>();
    kv_reduce_kernel<<<(B_ * D_ * D_) / 256, 256>>>();
    // 5. out = rowscale * (phi_q @ KV)
    out_gemm_kernel<<<dim3(N_ / 64, D_ / 64, B_), 256>>>(out);
}

// round 2
// speedup vs baseline: 1.5823x; 1.5823x over previous
#include <cuda_runtime.h>
#include <mma.h>
#include <math.h>
using namespace nvcuda;

// Problem constants
constexpr int B_ = 16;
constexpr int N_ = 4096;
constexpr int D_ = 256;
constexpr float EPS_ = 1e-6f;
constexpr int SPLITK = 8;

// GEMM tiling
constexpr int BM = 128, BN = 64, BK = 32;
constexpr int LDA  = BK + 4;   // 36  (row-major A tile [BM][LDA])
constexpr int LDB  = BN + 4;   // 68  (row-major B tile [BK][LDB])
constexpr int LDC  = BN + 4;   // 68  (C staging tile)
constexpr int LDA2 = BM + 4;   // 132 (col-major A tile for KV gemm: [BK][LDA2])

// -------- scratch (device globals; no allocation allowed) --------
__device__ float g_phi_q[(size_t)B_ * N_ * D_];          // 64 MB
__device__ float g_phi_k[(size_t)B_ * N_ * D_];          // 64 MB
__device__ float g_Ex  [(size_t)B_ * N_ * D_];           // 64 MB unnormalized softmax exp
__device__ float g_KVp [(size_t)SPLITK * B_ * D_ * D_];  // 32 MB split-K partials
__device__ float g_KV  [(size_t)B_ * D_ * D_];           // 4 MB
__device__ float g_rowscale[B_ * N_];
__device__ float g_colinv[B_ * D_];                      // 1/sumexp per (b,e)

__device__ __forceinline__ float sigmoidf_(float x) { return 1.f / (1.f + expf(-x)); }

using FragA  = wmma::fragment<wmma::matrix_a, 16, 16, 8, wmma::precision::tf32, wmma::row_major>;
using FragAc = wmma::fragment<wmma::matrix_a, 16, 16, 8, wmma::precision::tf32, wmma::col_major>;
using FragB  = wmma::fragment<wmma::matrix_b, 16, 16, 8, wmma::precision::tf32, wmma::row_major>;
using FragC  = wmma::fragment<wmma::accumulator, 16, 16, 8, float>;

// ============================================================================
// Kernel 1: phi = sigmoid(X @ W + b)   X in {Q,K} as [B*N, D], W [D,D], b [D]
// WMMA tf32, 128x64x32 tile, 8 warps of 2x2 16x16 fragments.
// ============================================================================
__global__ void phi_gemm_wmma(const float* __restrict__ Q,
                              const float* __restrict__ Kin,
                              const float* __restrict__ Wq,
                              const float* __restrict__ bq,
                              const float* __restrict__ Wk,
                              const float* __restrict__ bk)
{
    const bool is_k = (blockIdx.z != 0);
    const float* A  = is_k ? Kin : Q;
    const float* W  = is_k ? Wk  : Wq;
    const float* bv = is_k ? bk  : bq;
    float* C        = is_k ? g_phi_k : g_phi_q;

    const int m0 = blockIdx.x * BM;   // over B*N
    const int n0 = blockIdx.y * BN;   // over D

    __shared__ __align__(16) float smem[BM * LDC];   // 128*68 floats, reused for C
    float* As = smem;                 // [BM][LDA]
    float* Bs = smem + BM * LDA;      // [BK][LDB]
    float* Cs = smem;                 // reuse after k-loop

    const int tid = threadIdx.x;
    const int wid = tid >> 5;
    const int wm = (wid & 3) * 32;
    const int wn = (wid >> 2) * 32;

    FragC acc[2][2];
#pragma unroll
    for (int i = 0; i < 2; i++)
#pragma unroll
        for (int j = 0; j < 2; j++) wmma::fill_fragment(acc[i][j], 0.f);

    for (int k0 = 0; k0 < D_; k0 += BK) {
        {   // A tile: 128 x 32
            const int r = tid >> 3, c4 = (tid & 7) << 2;
#pragma unroll
            for (int i = 0; i < 4; i++) {
                float4 v = *(const float4*)&A[(size_t)(m0 + r + 32 * i) * D_ + k0 + c4];
                *(float4*)&As[(r + 32 * i) * LDA + c4] = v;
            }
        }
        {   // B tile: 32 x 64
            const int r = tid >> 4, c4 = (tid & 15) << 2;
#pragma unroll
            for (int i = 0; i < 2; i++) {
                float4 v = *(const float4*)&W[(size_t)(k0 + r + 16 * i) * D_ + n0 + c4];
                *(float4*)&Bs[(r + 16 * i) * LDB + c4] = v;
            }
        }
        __syncthreads();
#pragma unroll
        for (int kk = 0; kk < BK; kk += 8) {
            FragA a[2]; FragB b[2];
#pragma unroll
            for (int i = 0; i < 2; i++) {
                wmma::load_matrix_sync(a[i], &As[(wm + 16 * i) * LDA + kk], LDA);
#pragma unroll
                for (int t = 0; t < a[i].num_elements; t++)
                    a[i].x[t] = wmma::__float_to_tf32(a[i].x[t]);
            }
#pragma unroll
            for (int j = 0; j < 2; j++) {
                wmma::load_matrix_sync(b[j], &Bs[kk * LDB + wn + 16 * j], LDB);
#pragma unroll
                for (int t = 0; t < b[j].num_elements; t++)
                    b[j].x[t] = wmma::__float_to_tf32(b[j].x[t]);
            }
#pragma unroll
            for (int i = 0; i < 2; i++)
#pragma unroll
                for (int j = 0; j < 2; j++)
                    wmma::mma_sync(acc[i][j], a[i], b[j], acc[i][j]);
        }
        __syncthreads();
    }

#pragma unroll
    for (int i = 0; i < 2; i++)
#pragma unroll
        for (int j = 0; j < 2; j++)
            wmma::store_matrix_sync(&Cs[(wm + 16 * i) * LDC + wn + 16 * j],
                                    acc[i][j], LDC, wmma::mem_row_major);
    __syncthreads();

    {   // fused bias + sigmoid epilogue
        const int r = tid >> 4, c4 = (tid & 15) << 2;
        const float4 bb = *(const float4*)&bv[n0 + c4];
#pragma unroll
        for (int i = 0; i < 8; i++) {
            const int row = r + 16 * i;
            float4 v = *(float4*)&Cs[row * LDC + c4];
            float4 o;
            o.x = sigmoidf_(v.x + bb.x);
            o.y = sigmoidf_(v.y + bb.y);
            o.z = sigmoidf_(v.z + bb.z);
            o.w = sigmoidf_(v.w + bb.w);
            *(float4*)&C[(size_t)(m0 + row) * D_ + n0 + c4] = o;
        }
    }
}

// ============================================================================
// Kernel 2: rowscale[b,n] = sigmoid(rs)/(rs+eps), rs = sum_d phi_q[b,n,d]
// ============================================================================
__global__ void rowscale_kernel()
{
    const int row  = blockIdx.x * 8 + (threadIdx.x >> 5);
    const int lane = threadIdx.x & 31;
    const float* p = g_phi_q + (size_t)row * D_;
    float s = 0.f;
#pragma unroll
    for (int i = lane; i < D_; i += 32) s += p[i];
#pragma unroll
    for (int off = 16; off; off >>= 1) s += __shfl_xor_sync(0xffffffffu, s, off);
    if (lane == 0) g_rowscale[row] = sigmoidf_(s) / (s + EPS_);
}

// ============================================================================
// Kernel 3: column softmax (2 passes). Writes UNNORMALIZED exp to g_Ex and
// 1/sumexp to g_colinv (normalization folded into kv_reduce).
// x[b,n,d] = phi_k*V / (colsum_n phi_k + eps); softmax over n.
// ============================================================================
__global__ void col_softmax_kernel(const float* __restrict__ V)
{
    const int b  = blockIdx.x;
    const int td = threadIdx.x & 15;
    const int tn = threadIdx.x >> 4;           // 16 n-lanes
    const int d  = blockIdx.y * 16 + td;

    const float* Pk = g_phi_k + (size_t)b * N_ * D_ + d;
    const float* Vv = V       + (size_t)b * N_ * D_ + d;
    float*       Ex = g_Ex    + (size_t)b * N_ * D_ + d;

    __shared__ float s1[16][17], s2[16][17];

    // pass 1: colsum(phi_k) and max(phi_k*V)
    float csum = 0.f, ymax = -1e30f;
    for (int n = tn; n < N_; n += 16) {
        float pk = Pk[(size_t)n * D_];
        float y  = pk * Vv[(size_t)n * D_];
        csum += pk;
        ymax = fmaxf(ymax, y);
    }
    s1[tn][td] = csum; s2[tn][td] = ymax;
    __syncthreads();
    for (int h = 8; h; h >>= 1) {
        if (tn < h) {
            s1[tn][td] += s1[tn + h][td];
            s2[tn][td] = fmaxf(s2[tn][td], s2[tn + h][td]);
        }
        __syncthreads();
    }
    const float c    = 1.f / (s1[0][td] + EPS_);  // positive scale -> max commutes
    const float xmax = c * s2[0][td];
    __syncthreads();

    // pass 2: write exp(x - xmax), accumulate sumexp
    float se = 0.f;
    for (int n = tn; n < N_; n += 16) {
        float x = c * Pk[(size_t)n * D_] * Vv[(size_t)n * D_];
        float e = expf(x - xmax);
        Ex[(size_t)n * D_] = e;
        se += e;
    }
    s1[tn][td] = se;
    __syncthreads();
    for (int h = 8; h; h >>= 1) {
        if (tn < h) s1[tn][td] += s1[tn + h][td];
        __syncthreads();
    }
    if (tn == 0) g_colinv[b * D_ + d] = 1.f / s1[0][td];
}

// ============================================================================
// Kernel 4: KV partials = phi_k^T @ Ex per batch, split-K over N.
// matrix_a col_major reads phi_k[n][d] directly as A^T. Raw fp32 partial out.
// ============================================================================
__global__ void kv_gemm_wmma()
{
    const int b  = blockIdx.z / SPLITK;
    const int s  = blockIdx.z % SPLITK;
    const int d0 = blockIdx.x * BM;
    const int e0 = blockIdx.y * BN;

    const float* Pk = g_phi_k + (size_t)b * N_ * D_;
    const float* Ex = g_Ex    + (size_t)b * N_ * D_;
    float* Cout = g_KVp + ((size_t)s * B_ + b) * D_ * D_;

    __shared__ __align__(16) float As2[BK * LDA2];   // [n][d] -> col-major A
    __shared__ __align__(16) float Bs2[BK * LDB];    // [n][e]

    const int tid = threadIdx.x;
    const int wid = tid >> 5;
    const int wm = (wid & 3) * 32;
    const int wn = (wid >> 2) * 32;

    FragC acc[2][2];
#pragma unroll
    for (int i = 0; i < 2; i++)
#pragma unroll
        for (int j = 0; j < 2; j++) wmma::fill_fragment(acc[i][j], 0.f);

    const int nbeg = s * (N_ / SPLITK);
    const int nend = nbeg + (N_ / SPLITK);
    for (int n0 = nbeg; n0 < nend; n0 += BK) {
        {   // A tile: 32 n-rows x 128 d
            const int r = tid >> 5, c4 = (tid & 31) << 2;
#pragma unroll
            for (int i = 0; i < 4; i++) {
                float4 v = *(const float4*)&Pk[(size_t)(n0 + r + 8 * i) * D_ + d0 + c4];
                *(float4*)&As2[(r + 8 * i) * LDA2 + c4] = v;
            }
        }
        {   // B tile: 32 n-rows x 64 e
            const int r = tid >> 4, c4 = (tid & 15) << 2;
#pragma unroll
            for (int i = 0; i < 2; i++) {
                float4 v = *(const float4*)&Ex[(size_t)(n0 + r + 16 * i) * D_ + e0 + c4];
                *(float4*)&Bs2[(r + 16 * i) * LDB + c4] = v;
            }
        }
        __syncthreads();
#pragma unroll
        for (int kk = 0; kk < BK; kk += 8) {
            FragAc a[2]; FragB b2[2];
#pragma unroll
            for (int i = 0; i < 2; i++) {
                wmma::load_matrix_sync(a[i], &As2[kk * LDA2 + wm + 16 * i], LDA2);
#pragma unroll
                for (int t = 0; t < a[i].num_elements; t++)
                    a[i].x[t] = wmma::__float_to_tf32(a[i].x[t]);
            }
#pragma unroll
            for (int j = 0; j < 2; j++) {
                wmma::load_matrix_sync(b2[j], &Bs2[kk * LDB + wn + 16 * j], LDB);
#pragma unroll
                for (int t = 0; t < b2[j].num_elements; t++)
                    b2[j].x[t] = wmma::__float_to_tf32(b2[j].x[t]);
            }
#pragma unroll
            for (int i = 0; i < 2; i++)
#pragma unroll
                for (int j = 0; j < 2; j++)
                    wmma::mma_sync(acc[i][j], a[i], b2[j], acc[i][j]);
        }
        __syncthreads();
    }

#pragma unroll
    for (int i = 0; i < 2; i++)
#pragma unroll
        for (int j = 0; j < 2; j++)
            wmma::store_matrix_sync(&Cout[(size_t)(d0 + wm + 16 * i) * D_ + e0 + wn + 16 * j],
                                    acc[i][j], D_, wmma::mem_row_major);
}

// Deterministic split-K reduce + softmax column normalization
__global__ void kv_reduce_kernel()
{
    const size_t i = (size_t)blockIdx.x * 256 + threadIdx.x;  // over B*D*D
    const size_t stride = (size_t)B_ * D_ * D_;
    float s = 0.f;
#pragma unroll
    for (int p = 0; p < SPLITK; p++) s += g_KVp[p * stride + i];
    const int b = (int)(i / (D_ * D_));
    const int e = (int)(i % D_);
    g_KV[i] = s * g_colinv[b * D_ + e];
}

// ============================================================================
// Kernel 5: out[b,n,e] = rowscale[b,n] * (phi_q[b] @ KV[b])[n,e]
// ============================================================================
__global__ void out_gemm_wmma(float* __restrict__ out)
{
    const int b  = blockIdx.z;
    const int m0 = blockIdx.x * BM;   // n within batch
    const int n0 = blockIdx.y * BN;   // e

    const float* Aq = g_phi_q + (size_t)b * N_ * D_;
    const float* KV = g_KV    + (size_t)b * D_ * D_;

    __shared__ __align__(16) float smem[BM * LDC];
    float* As = smem;
    float* Bs = smem + BM * LDA;
    float* Cs = smem;

    const int tid = threadIdx.x;
    const int wid = tid >> 5;
    const int wm = (wid & 3) * 32;
    const int wn = (wid >> 2) * 32;

    FragC acc[2][2];
#pragma unroll
    for (int i = 0; i < 2; i++)
#pragma unroll
        for (int j = 0; j < 2; j++) wmma::fill_fragment(acc[i][j], 0.f);

    for (int k0 = 0; k0 < D_; k0 += BK) {
        {
            const int r = tid >> 3, c4 = (tid & 7) << 2;
#pragma unroll
            for (int i = 0; i < 4; i++) {
                float4 v = *(const float4*)&Aq[(size_t)(m0 + r + 32 * i) * D_ + k0 + c4];
                *(float4*)&As[(r + 32 * i) * LDA + c4] = v;
            }
        }
        {
            const int r = tid >> 4, c4 = (tid & 15) << 2;
#pragma unroll
            for (int i = 0; i < 2; i++) {
                float4 v = *(const float4*)&KV[(size_t)(k0 + r + 16 * i) * D_ + n0 + c4];
                *(float4*)&Bs[(r + 16 * i) * LDB + c4] = v;
            }
        }
        __syncthreads();
#pragma unroll
        for (int kk = 0; kk < BK; kk += 8) {
            FragA a[2]; FragB b2[2];
#pragma unroll
            for (int i = 0; i < 2; i++) {
                wmma::load_matrix_sync(a[i], &As[(wm + 16 * i) * LDA + kk], LDA);
#pragma unroll
                for (int t = 0; t < a[i].num_elements; t++)
                    a[i].x[t] = wmma::__float_to_tf32(a[i].x[t]);
            }
#pragma unroll
            for (int j = 0; j < 2; j++) {
                wmma::load_matrix_sync(b2[j], &Bs[kk * LDB + wn + 16 * j], LDB);
#pragma unroll
                for (int t = 0; t < b2[j].num_elements; t++)
                    b2[j].x[t] = wmma::__float_to_tf32(b2[j].x[t]);
            }
#pragma unroll
            for (int i = 0; i < 2; i++)
#pragma unroll
                for (int j = 0; j < 2; j++)
                    wmma::mma_sync(acc[i][j], a[i], b2[j], acc[i][j]);
        }
        __syncthreads();
    }

#pragma unroll
    for (int i = 0; i < 2; i++)
#pragma unroll
        for (int j = 0; j < 2; j++)
            wmma::store_matrix_sync(&Cs[(wm + 16 * i) * LDC + wn + 16 * j],
                                    acc[i][j], LDC, wmma::mem_row_major);
    __syncthreads();

    {   // fused rowscale epilogue
        const int r = tid >> 4, c4 = (tid & 15) << 2;
#pragma unroll
        for (int i = 0; i < 8; i++) {
            const int row = r + 16 * i;
            const float sc = g_rowscale[b * N_ + m0 + row];
            float4 v = *(float4*)&Cs[row * LDC + c4];
            *(float4*)&out[((size_t)b * N_ + m0 + row) * D_ + n0 + c4] =
                make_float4(sc * v.x, sc * v.y, sc * v.z, sc * v.w);
        }
    }
}

// ============================================================================
// Launch: inputs per metadata order: Q, K, V, Wq, bq, Wk, bk
// ============================================================================
extern "C" void kernel_launch(void* const* d_in, const int* in_sizes, int n_in,
                              void* d_out, int out_size)
{
    const float* Q  = (const float*)d_in[0];
    const float* K  = (const float*)d_in[1];
    const float* V  = (const float*)d_in[2];
    const float* Wq = (const float*)d_in[3];
    const float* bq = (const float*)d_in[4];
    const float* Wk = (const float*)d_in[5];
    const float* bk = (const float*)d_in[6];
    float* out = (float*)d_out;

    phi_gemm_wmma<<<dim3((B_ * N_) / BM, D_ / BN, 2), 256>>>(Q, K, Wq, bq, Wk, bk);
    rowscale_kernel<<<(B_ * N_) / 8, 256>>>();
    col_softmax_kernel<<<dim3(B_, D_ / 16), 256>>>(V);
    kv_gemm_wmma<<<dim3(D_ / BM, D_ / BN, B_ * SPLITK), 256>>>();
    kv_reduce_kernel<<<(B_ * D_ * D_) / 256, 256>>>();
    out_gemm_wmma<<<dim3(N_ / BM, D_ / BN, B_), 256>>>(out);
}

// round 6
// speedup vs baseline: 4.2672x; 2.6968x over previous
#include <cuda_runtime.h>
#include <cuda_bf16.h>
#include <mma.h>
#include <math.h>
using namespace nvcuda;

// Problem constants
constexpr int B_ = 16;
constexpr int N_ = 4096;
constexpr int D_ = 256;
constexpr float EPS_ = 1e-6f;
constexpr int SPLITK = 8;

// GEMM tiling
constexpr int BM = 128, BN = 128, BK = 32;
constexpr int LDAH = BK + 8;    // 40 halves  (row-major A tile [BM][LDAH])
constexpr int LDBH = BN + 8;    // 136 halves (row-major B tile [BK][LDBH]; also col-major A for kv)
constexpr int LDC  = BN + 4;    // 132 floats (epilogue staging, 64 rows)
constexpr int NMBLK = (B_ * N_) / BM;   // 512

// -------- scratch (device globals; no allocation allowed) --------
__device__ __nv_bfloat16 g_phi_q[(size_t)B_ * N_ * D_];   // 32 MB
__device__ __nv_bfloat16 g_phi_k[(size_t)B_ * N_ * D_];   // 32 MB
__device__ __nv_bfloat16 g_Ex  [(size_t)B_ * N_ * D_];    // 32 MB (unnormalized exp)
__device__ float g_KVp [(size_t)SPLITK * B_ * D_ * D_];   // 33.5 MB split-K partials
__device__ __nv_bfloat16 g_KVh[(size_t)B_ * D_ * D_];     // 2 MB (colinv folded)
__device__ float g_colp[NMBLK * D_];                      // per-mblock colsum partials (phi_k)
__device__ float g_rowp[B_ * N_ * 2];                     // per-(row, yhalf) rowsum partials (phi_q)
__device__ float g_colinv[B_ * D_];                       // 1/sumexp per (b,e)

__device__ __forceinline__ float sigmoid_fast(float x) {
    return __fdividef(1.f, 1.f + __expf(-x));
}

using HA  = wmma::fragment<wmma::matrix_a, 16, 16, 16, __nv_bfloat16, wmma::row_major>;
using HAc = wmma::fragment<wmma::matrix_a, 16, 16, 16, __nv_bfloat16, wmma::col_major>;
using HB  = wmma::fragment<wmma::matrix_b, 16, 16, 16, __nv_bfloat16, wmma::row_major>;
using HC  = wmma::fragment<wmma::accumulator, 16, 16, 16, float>;

// ============================================================================
// Kernel 1: phi = sigmoid(X @ W + b), bf16 WMMA 128x128x32, 8 warps (4m x 2n),
// each warp 32x64 (2x4 frags). Epilogue: bias+sigmoid -> bf16 phi, plus
// block-partial colsums (phi_k) and per-row rowsums (phi_q).
// ============================================================================
__global__ __launch_bounds__(256, 2)
void phi_gemm_bf16(const float* __restrict__ Q,
                   const float* __restrict__ Kin,
                   const float* __restrict__ Wq,
                   const float* __restrict__ bq,
                   const float* __restrict__ Wk,
                   const float* __restrict__ bk)
{
    const bool is_k = (blockIdx.z != 0);
    const float* A  = is_k ? Kin : Q;
    const float* W  = is_k ? Wk  : Wq;
    const float* bv = is_k ? bk  : bq;
    __nv_bfloat16* C = is_k ? g_phi_k : g_phi_q;

    const int m0 = blockIdx.x * BM;   // over B*N
    const int n0 = blockIdx.y * BN;   // over D (0 or 128)

    __shared__ __align__(16) char sraw[64 * LDC * 4];  // 33792 B (union)
    __nv_bfloat16* Ah = (__nv_bfloat16*)sraw;                       // [BM][LDAH]
    __nv_bfloat16* Bh = (__nv_bfloat16*)(sraw + BM * LDAH * 2);     // [BK][LDBH]
    float* Cs = (float*)sraw;                                       // [64][LDC]

    const int tid = threadIdx.x;
    const int wid = tid >> 5;
    const int lane = tid & 31;
    const int wm = (wid & 3) * 32;
    const int wn = (wid >> 2) * 64;

    HC acc[2][4];
#pragma unroll
    for (int i = 0; i < 2; i++)
#pragma unroll
        for (int j = 0; j < 4; j++) wmma::fill_fragment(acc[i][j], 0.f);

    for (int k0 = 0; k0 < D_; k0 += BK) {
        // A tile: 128x32 fp32 -> bf16
#pragma unroll
        for (int j = 0; j < 4; j++) {
            const int f = tid + 256 * j;           // 1024 float4s
            const int r = f >> 3, c = (f & 7) * 4;
            float4 v = *(const float4*)&A[(size_t)(m0 + r) * D_ + k0 + c];
            *(__nv_bfloat162*)&Ah[r * LDAH + c]     = __floats2bfloat162_rn(v.x, v.y);
            *(__nv_bfloat162*)&Ah[r * LDAH + c + 2] = __floats2bfloat162_rn(v.z, v.w);
        }
        // B tile: 32x128 fp32 -> bf16
#pragma unroll
        for (int j = 0; j < 4; j++) {
            const int f = tid + 256 * j;
            const int r = f >> 5, c = (f & 31) * 4;
            float4 v = *(const float4*)&W[(size_t)(k0 + r) * D_ + n0 + c];
            *(__nv_bfloat162*)&Bh[r * LDBH + c]     = __floats2bfloat162_rn(v.x, v.y);
            *(__nv_bfloat162*)&Bh[r * LDBH + c + 2] = __floats2bfloat162_rn(v.z, v.w);
        }
        __syncthreads();
#pragma unroll
        for (int kk = 0; kk < BK; kk += 16) {
            HA a[2]; HB b[4];
#pragma unroll
            for (int i = 0; i < 2; i++)
                wmma::load_matrix_sync(a[i], &Ah[(wm + 16 * i) * LDAH + kk], LDAH);
#pragma unroll
            for (int j = 0; j < 4; j++)
                wmma::load_matrix_sync(b[j], &Bh[kk * LDBH + wn + 16 * j], LDBH);
#pragma unroll
            for (int i = 0; i < 2; i++)
#pragma unroll
                for (int j = 0; j < 4; j++)
                    wmma::mma_sync(acc[i][j], a[i], b[j], acc[i][j]);
        }
        __syncthreads();
    }

    // ---- epilogue: two 64-row halves staged through smem ----
    const int c4 = lane * 4;      // 0..124 (warp w handles rows {w + 8i})
    const float4 bb = *(const float4*)&bv[n0 + c4];
    float4 colsum = make_float4(0.f, 0.f, 0.f, 0.f);

#pragma unroll
    for (int h = 0; h < 2; h++) {
        if (((wid >> 1) & 1) == h) {
#pragma unroll
            for (int i = 0; i < 2; i++)
#pragma unroll
                for (int j = 0; j < 4; j++)
                    wmma::store_matrix_sync(&Cs[(wm - 64 * h + 16 * i) * LDC + wn + 16 * j],
                                            acc[i][j], LDC, wmma::mem_row_major);
        }
        __syncthreads();
#pragma unroll
        for (int i = 0; i < 8; i++) {
            const int r = wid + 8 * i;            // local row 0..63
            float4 v = *(float4*)&Cs[r * LDC + c4];
            float4 o;
            o.x = sigmoid_fast(v.x + bb.x);
            o.y = sigmoid_fast(v.y + bb.y);
            o.z = sigmoid_fast(v.z + bb.z);
            o.w = sigmoid_fast(v.w + bb.w);
            const size_t goff = (size_t)(m0 + 64 * h + r) * D_ + n0 + c4;
            *(__nv_bfloat162*)&C[goff]     = __floats2bfloat162_rn(o.x, o.y);
            *(__nv_bfloat162*)&C[goff + 2] = __floats2bfloat162_rn(o.z, o.w);
            if (is_k) {
                colsum.x += o.x; colsum.y += o.y; colsum.z += o.z; colsum.w += o.w;
            } else {
                float rs = o.x + o.y + o.z + o.w;
#pragma unroll
                for (int off = 16; off; off >>= 1)
                    rs += __shfl_xor_sync(0xffffffffu, rs, off);
                if (lane == 0)
                    g_rowp[(size_t)(m0 + 64 * h + r) * 2 + blockIdx.y] = rs;
            }
        }
        __syncthreads();
    }

    if (is_k) {
        // cross-warp column reduce via smem (reuse Cs region: [8][128] floats)
        float* cred = (float*)sraw;
        *(float4*)&cred[wid * 128 + c4] = colsum;
        __syncthreads();
        if (tid < 32) {
            float4 s = make_float4(0.f, 0.f, 0.f, 0.f);
#pragma unroll
            for (int w = 0; w < 8; w++) {
                float4 v = *(float4*)&cred[w * 128 + tid * 4];
                s.x += v.x; s.y += v.y; s.z += v.z; s.w += v.w;
            }
            *(float4*)&g_colp[(size_t)blockIdx.x * D_ + n0 + tid * 4] = s;
        }
    }
}

// ============================================================================
// Kernel 2: single-pass column softmax (no max subtraction; |x|<=|v| bounded).
// colsum from g_colp partials. Writes unnormalized exp (bf16) + colinv.
// grid (B, D/32), 1024 threads: 16 d-pair lanes x 64 n-lanes.
// ============================================================================
__global__ __launch_bounds__(1024, 1)
void col_softmax_kernel(const float* __restrict__ V)
{
    const int b   = blockIdx.x;
    const int td  = threadIdx.x & 15;          // d-pair lane
    const int tn  = threadIdx.x >> 4;          // 0..63
    const int d0  = blockIdx.y * 32 + 2 * td;

    __shared__ float2 red[64][17];

    // colsum for this block's 32 d's from 32 m-block partials
    float2 cs = make_float2(0.f, 0.f);
    if (tn < 32)
        cs = *(const float2*)&g_colp[(size_t)(b * 32 + tn) * D_ + d0];
    red[tn][td] = cs;
    __syncthreads();
#pragma unroll
    for (int h = 32; h; h >>= 1) {
        if (tn < h) {
            red[tn][td].x += red[tn + h][td].x;
            red[tn][td].y += red[tn + h][td].y;
        }
        __syncthreads();
    }
    const float cx = __fdividef(1.f, red[0][td].x + EPS_);
    const float cy = __fdividef(1.f, red[0][td].y + EPS_);
    __syncthreads();

    const __nv_bfloat16* Pk = g_phi_k + (size_t)b * N_ * D_ + d0;
    const float*         Vv = V       + (size_t)b * N_ * D_ + d0;
    __nv_bfloat16*       Ex = g_Ex    + (size_t)b * N_ * D_ + d0;

    float2 se = make_float2(0.f, 0.f);
    for (int n = tn; n < N_; n += 64) {
        const size_t off = (size_t)n * D_;
        __nv_bfloat162 pk2 = *(const __nv_bfloat162*)(Pk + off);
        float2 v2 = *(const float2*)(Vv + off);
        float ex = __expf(cx * __bfloat162float(pk2.x) * v2.x);
        float ey = __expf(cy * __bfloat162float(pk2.y) * v2.y);
        *(__nv_bfloat162*)(Ex + off) = __floats2bfloat162_rn(ex, ey);
        se.x += ex; se.y += ey;
    }
    red[tn][td] = se;
    __syncthreads();
#pragma unroll
    for (int h = 32; h; h >>= 1) {
        if (tn < h) {
            red[tn][td].x += red[tn + h][td].x;
            red[tn][td].y += red[tn + h][td].y;
        }
        __syncthreads();
    }
    if (tn == 0) {
        g_colinv[b * D_ + d0]     = __fdividef(1.f, red[0][td].x);
        g_colinv[b * D_ + d0 + 1] = __fdividef(1.f, red[0][td].y);
    }
}

// ============================================================================
// Kernel 3: KV partials = phi_k^T @ Ex per batch, split-K over N, bf16 WMMA.
// A read col-major directly from phi_k[n][d]. grid (2, 2, B*SPLITK).
// ============================================================================
__global__ __launch_bounds__(256, 2)
void kv_gemm_bf16()
{
    const int b  = blockIdx.z / SPLITK;
    const int s  = blockIdx.z % SPLITK;
    const int d0 = blockIdx.x * BM;
    const int e0 = blockIdx.y * BN;

    const __nv_bfloat16* Pk = g_phi_k + (size_t)b * N_ * D_;
    const __nv_bfloat16* Ex = g_Ex    + (size_t)b * N_ * D_;
    float* Cout = g_KVp + ((size_t)s * B_ + b) * D_ * D_;

    __shared__ __align__(16) __nv_bfloat16 As2[BK * LDBH];  // [n][d] col-major A
    __shared__ __align__(16) __nv_bfloat16 Bs2[BK * LDBH];  // [n][e]

    const int tid = threadIdx.x;
    const int wid = tid >> 5;
    const int wm = (wid & 3) * 32;
    const int wn = (wid >> 2) * 64;

    HC acc[2][4];
#pragma unroll
    for (int i = 0; i < 2; i++)
#pragma unroll
        for (int j = 0; j < 4; j++) wmma::fill_fragment(acc[i][j], 0.f);

    const int nbeg = s * (N_ / SPLITK);
    for (int n0 = nbeg; n0 < nbeg + N_ / SPLITK; n0 += BK) {
#pragma unroll
        for (int j = 0; j < 2; j++) {
            const int f = tid + 256 * j;          // 512 uint4s (32 rows x 16)
            const int r = f >> 4, c8 = (f & 15) * 8;
            *(uint4*)&As2[r * LDBH + c8] = *(const uint4*)&Pk[(size_t)(n0 + r) * D_ + d0 + c8];
            *(uint4*)&Bs2[r * LDBH + c8] = *(const uint4*)&Ex[(size_t)(n0 + r) * D_ + e0 + c8];
        }
        __syncthreads();
#pragma unroll
        for (int kk = 0; kk < BK; kk += 16) {
            HAc a[2]; HB b2[4];
#pragma unroll
            for (int i = 0; i < 2; i++)
                wmma::load_matrix_sync(a[i], &As2[kk * LDBH + wm + 16 * i], LDBH);
#pragma unroll
            for (int j = 0; j < 4; j++)
                wmma::load_matrix_sync(b2[j], &Bs2[kk * LDBH + wn + 16 * j], LDBH);
#pragma unroll
            for (int i = 0; i < 2; i++)
#pragma unroll
                for (int j = 0; j < 4; j++)
                    wmma::mma_sync(acc[i][j], a[i], b2[j], acc[i][j]);
        }
        __syncthreads();
    }

#pragma unroll
    for (int i = 0; i < 2; i++)
#pragma unroll
        for (int j = 0; j < 4; j++)
            wmma::store_matrix_sync(&Cout[(size_t)(d0 + wm + 16 * i) * D_ + e0 + wn + 16 * j],
                                    acc[i][j], D_, wmma::mem_row_major);
}

// Deterministic split-K reduce + softmax normalization -> bf16 KV
__global__ void kv_reduce_kernel()
{
    const size_t i4 = ((size_t)blockIdx.x * 256 + threadIdx.x) * 4;
    const size_t stride = (size_t)B_ * D_ * D_;
    float4 s = make_float4(0.f, 0.f, 0.f, 0.f);
#pragma unroll
    for (int p = 0; p < SPLITK; p++) {
        float4 v = *(const float4*)&g_KVp[p * stride + i4];
        s.x += v.x; s.y += v.y; s.z += v.z; s.w += v.w;
    }
    const int b = (int)(i4 / (D_ * D_));
    const int e = (int)(i4 % D_);
    float4 ci = *(const float4*)&g_colinv[b * D_ + e];
    *(__nv_bfloat162*)&g_KVh[i4]     = __floats2bfloat162_rn(s.x * ci.x, s.y * ci.y);
    *(__nv_bfloat162*)&g_KVh[i4 + 2] = __floats2bfloat162_rn(s.z * ci.z, s.w * ci.w);
}

// ============================================================================
// Kernel 4: out = (rowscale * phi_q) @ KVh ; rowscale folded into A-load so
// accumulator fragments store straight to d_out (fp32). grid (N/128, 2, B).
// ============================================================================
__global__ __launch_bounds__(256, 2)
void out_gemm_bf16(float* __restrict__ out)
{
    const int b  = blockIdx.z;
    const int m0 = blockIdx.x * BM;   // n within batch
    const int e0 = blockIdx.y * BN;

    const __nv_bfloat16* Aq = g_phi_q + (size_t)b * N_ * D_;
    const __nv_bfloat16* KV = g_KVh   + (size_t)b * D_ * D_;

    __shared__ __align__(16) __nv_bfloat16 Ah[BM * LDAH];
    __shared__ __align__(16) __nv_bfloat16 Bh[BK * LDBH];
    __shared__ float scf[BM];

    const int tid = threadIdx.x;
    const int wid = tid >> 5;
    const int wm = (wid & 3) * 32;
    const int wn = (wid >> 2) * 64;

    if (tid < BM) {
        const size_t row = (size_t)b * N_ + m0 + tid;
        float rs = g_rowp[row * 2] + g_rowp[row * 2 + 1];
        scf[tid] = sigmoid_fast(rs) * __fdividef(1.f, rs + EPS_);
    }

    HC acc[2][4];
#pragma unroll
    for (int i = 0; i < 2; i++)
#pragma unroll
        for (int j = 0; j < 4; j++) wmma::fill_fragment(acc[i][j], 0.f);
    __syncthreads();

    for (int k0 = 0; k0 < D_; k0 += BK) {
        // A: 128x32 bf16, scaled by scf[row]
#pragma unroll
        for (int j = 0; j < 2; j++) {
            const int f = tid + 256 * j;          // 512 uint4s (128 rows x 4)
            const int r = f >> 2, c8 = (f & 3) * 8;
            uint4 raw = *(const uint4*)&Aq[(size_t)(m0 + r) * D_ + k0 + c8];
            const float sc = scf[r];
            __nv_bfloat162* hp = (__nv_bfloat162*)&raw;
            uint4 outw;
            __nv_bfloat162* op = (__nv_bfloat162*)&outw;
#pragma unroll
            for (int t = 0; t < 4; t++) {
                float2 f2 = __bfloat1622float2(hp[t]);
                op[t] = __floats2bfloat162_rn(f2.x * sc, f2.y * sc);
            }
            *(uint4*)&Ah[r * LDAH + c8] = outw;
        }
        // B: 32x128 bf16 copy
#pragma unroll
        for (int j = 0; j < 2; j++) {
            const int f = tid + 256 * j;
            const int r = f >> 4, c8 = (f & 15) * 8;
            *(uint4*)&Bh[r * LDBH + c8] = *(const uint4*)&KV[(size_t)(k0 + r) * D_ + e0 + c8];
        }
        __syncthreads();
#pragma unroll
        for (int kk = 0; kk < BK; kk += 16) {
            HA a[2]; HB b2[4];
#pragma unroll
            for (int i = 0; i < 2; i++)
                wmma::load_matrix_sync(a[i], &Ah[(wm + 16 * i) * LDAH + kk], LDAH);
#pragma unroll
            for (int j = 0; j < 4; j++)
                wmma::load_matrix_sync(b2[j], &Bh[kk * LDBH + wn + 16 * j], LDBH);
#pragma unroll
            for (int i = 0; i < 2; i++)
#pragma unroll
                for (int j = 0; j < 4; j++)
                    wmma::mma_sync(acc[i][j], a[i], b2[j], acc[i][j]);
        }
        __syncthreads();
    }

#pragma unroll
    for (int i = 0; i < 2; i++)
#pragma unroll
        for (int j = 0; j < 4; j++)
            wmma::store_matrix_sync(&out[((size_t)b * N_ + m0 + wm + 16 * i) * D_ + e0 + wn + 16 * j],
                                    acc[i][j], D_, wmma::mem_row_major);
}

// ============================================================================
// Launch: inputs per metadata order: Q, K, V, Wq, bq, Wk, bk
// ============================================================================
extern "C" void kernel_launch(void* const* d_in, const int* in_sizes, int n_in,
                              void* d_out, int out_size)
{
    const float* Q  = (const float*)d_in[0];
    const float* K  = (const float*)d_in[1];
    const float* V  = (const float*)d_in[2];
    const float* Wq = (const float*)d_in[3];
    const float* bq = (const float*)d_in[4];
    const float* Wk = (const float*)d_in[5];
    const float* bk = (const float*)d_in[6];
    float* out = (float*)d_out;

    phi_gemm_bf16<<<dim3(NMBLK, D_ / BN, 2), 256>>>(Q, K, Wq, bq, Wk, bk);
    col_softmax_kernel<<<dim3(B_, D_ / 32), 1024>>>(V);
    kv_gemm_bf16<<<dim3(D_ / BM, D_ / BN, B_ * SPLITK), 256>>>();
    kv_reduce_kernel<<<(B_ * D_ * D_) / 1024, 256>>>();
    out_gemm_bf16<<<dim3(N_ / BM, D_ / BN, B_), 256>>>(out);
}

// round 8
// speedup vs baseline: 4.4578x; 1.0447x over previous
#include <cuda_runtime.h>
#include <cuda_bf16.h>
#include <mma.h>
#include <math.h>
#include <cstdint>
using namespace nvcuda;

// Problem constants
constexpr int B_ = 16;
constexpr int N_ = 4096;
constexpr int D_ = 256;
constexpr float EPS_ = 1e-6f;
constexpr int SPLITK = 8;

// Tiling
constexpr int LDAH = 40;    // 32 + 8 halves (A tiles [rows][BK])
constexpr int LDW  = 264;   // 256 + 8 halves (256-wide B tiles)
constexpr int LDKV = 136;   // 128 + 8 halves (kv tiles)
constexpr int LDC  = 132;   // floats, epilogue staging (64 x 132)
constexpr int NMBLK = (B_ * N_) / 64;   // 1024 row-blocks of 64

// -------- scratch (device globals; no allocation allowed) --------
__device__ __nv_bfloat16 g_phi_q[(size_t)B_ * N_ * D_];   // 32 MB
__device__ __nv_bfloat16 g_phi_k[(size_t)B_ * N_ * D_];   // 32 MB
__device__ __nv_bfloat16 g_Ex  [(size_t)B_ * N_ * D_];    // 32 MB (unnormalized exp)
__device__ float g_KVp [(size_t)SPLITK * B_ * D_ * D_];   // 33.5 MB split-K partials
__device__ __nv_bfloat16 g_KVh[(size_t)B_ * D_ * D_];     // 2 MB (colinv folded)
__device__ __nv_bfloat16 g_Wq_h[D_ * D_];                 // bf16 weights
__device__ __nv_bfloat16 g_Wk_h[D_ * D_];
__device__ float g_colp[NMBLK * D_];                      // per-rowblock colsum partials (phi_k)
__device__ float g_rowp[B_ * N_ * 2];                     // per-(row, half) rowsum partials (phi_q)
__device__ float g_colinv[B_ * D_];                       // 1/sumexp per (b,e)

__device__ __forceinline__ float sigmoid_fast(float x) {
    return __fdividef(1.f, 1.f + __expf(-x));
}
__device__ __forceinline__ void cp_async16(void* sp, const void* gp) {
    unsigned int s = (unsigned int)__cvta_generic_to_shared(sp);
    asm volatile("cp.async.cg.shared.global [%0], [%1], 16;\n" :: "r"(s), "l"(gp));
}
__device__ __forceinline__ void cp_commit() {
    asm volatile("cp.async.commit_group;\n");
}
__device__ __forceinline__ void cp_wait1() {
    asm volatile("cp.async.wait_group 1;\n");
}
__device__ __forceinline__ void cp_wait0() {
    asm volatile("cp.async.wait_group 0;\n");
}

using HA  = wmma::fragment<wmma::matrix_a, 16, 16, 16, __nv_bfloat16, wmma::row_major>;
using HAc = wmma::fragment<wmma::matrix_a, 16, 16, 16, __nv_bfloat16, wmma::col_major>;
using HB  = wmma::fragment<wmma::matrix_b, 16, 16, 16, __nv_bfloat16, wmma::row_major>;
using HC  = wmma::fragment<wmma::accumulator, 16, 16, 16, float>;

// ============================================================================
// Kernel 0: convert W -> bf16 (tiny; once per launch)
// ============================================================================
__global__ void convert_w(const float* __restrict__ Wq, const float* __restrict__ Wk)
{
    const int i4 = (blockIdx.x * 256 + threadIdx.x) * 4;
    float4 a = *(const float4*)&Wq[i4];
    float4 b = *(const float4*)&Wk[i4];
    *(__nv_bfloat162*)&g_Wq_h[i4]     = __floats2bfloat162_rn(a.x, a.y);
    *(__nv_bfloat162*)&g_Wq_h[i4 + 2] = __floats2bfloat162_rn(a.z, a.w);
    *(__nv_bfloat162*)&g_Wk_h[i4]     = __floats2bfloat162_rn(b.x, b.y);
    *(__nv_bfloat162*)&g_Wk_h[i4 + 2] = __floats2bfloat162_rn(b.z, b.w);
}

// ============================================================================
// Kernel 1: phi = sigmoid(X @ W + b). 64x256x32 tile, 8 warps (2m x 4n),
// double-buffered (A: LDG fp32->cvt->STS, W: cp.async bf16).
// Epilogue (two 128-col halves): bf16 phi + rowsum partials (q) /
// colsum partials (k).
// ============================================================================
__global__ __launch_bounds__(256, 2)
void phi_gemm_bf16(const float* __restrict__ Q,
                   const float* __restrict__ Kin,
                   const float* __restrict__ bq,
                   const float* __restrict__ bk)
{
    const bool is_k = (blockIdx.z != 0);
    const float* A  = is_k ? Kin : Q;
    const __nv_bfloat16* Wh = is_k ? g_Wk_h : g_Wq_h;
    const float* bv = is_k ? bk  : bq;
    __nv_bfloat16* C = is_k ? g_phi_k : g_phi_q;

    const int m0 = blockIdx.x * 64;   // over B*N

    __shared__ __align__(16) char sm[44032];
    __nv_bfloat16* Ah[2] = { (__nv_bfloat16*)sm,
                             (__nv_bfloat16*)(sm + 5120) };
    __nv_bfloat16* Wt[2] = { (__nv_bfloat16*)(sm + 10240),
                             (__nv_bfloat16*)(sm + 10240 + 16896) };
    float* Cs = (float*)sm;           // 64 x 132 (reused after k-loop)

    const int tid = threadIdx.x;
    const int wid = tid >> 5;
    const int lane = tid & 31;
    const int wm = (wid & 1) * 32;
    const int wn = (wid >> 1) * 64;

    HC acc[2][4];
#pragma unroll
    for (int i = 0; i < 2; i++)
#pragma unroll
        for (int j = 0; j < 4; j++) wmma::fill_fragment(acc[i][j], 0.f);

    // tile loader: kt-th 32-slice into buffer bb
    auto load_tile = [&](int kt, int bb) {
        const int k0 = kt * 32;
#pragma unroll
        for (int j = 0; j < 2; j++) {               // A: 512 float4 total
            const int f = tid + 256 * j;
            const int r = f >> 3, c = (f & 7) * 4;
            float4 v = *(const float4*)&A[(size_t)(m0 + r) * D_ + k0 + c];
            *(__nv_bfloat162*)&Ah[bb][r * LDAH + c]     = __floats2bfloat162_rn(v.x, v.y);
            *(__nv_bfloat162*)&Ah[bb][r * LDAH + c + 2] = __floats2bfloat162_rn(v.z, v.w);
        }
#pragma unroll
        for (int j = 0; j < 4; j++) {               // W: 1024 16B chunks
            const int f = tid + 256 * j;
            const int r = f >> 5, c8 = (f & 31) * 8;
            cp_async16(&Wt[bb][r * LDW + c8], &Wh[(size_t)(k0 + r) * D_ + c8]);
        }
        cp_commit();
    };

    load_tile(0, 0);
    for (int kt = 0; kt < 8; kt++) {
        if (kt < 7) { load_tile(kt + 1, (kt + 1) & 1); cp_wait1(); }
        else        { cp_wait0(); }
        __syncthreads();
        const __nv_bfloat16* Ab = Ah[kt & 1];
        const __nv_bfloat16* Wb = Wt[kt & 1];
#pragma unroll
        for (int kk = 0; kk < 32; kk += 16) {
            HA a[2]; HB b[4];
#pragma unroll
            for (int i = 0; i < 2; i++)
                wmma::load_matrix_sync(a[i], &Ab[(wm + 16 * i) * LDAH + kk], LDAH);
#pragma unroll
            for (int j = 0; j < 4; j++)
                wmma::load_matrix_sync(b[j], &Wb[kk * LDW + wn + 16 * j], LDW);
#pragma unroll
            for (int i = 0; i < 2; i++)
#pragma unroll
                for (int j = 0; j < 4; j++)
                    wmma::mma_sync(acc[i][j], a[i], b[j], acc[i][j]);
        }
        __syncthreads();
    }

    // ---- epilogue: two 128-col halves through smem ----
#pragma unroll
    for (int h = 0; h < 2; h++) {
        if ((wid >> 2) == h) {
#pragma unroll
            for (int i = 0; i < 2; i++)
#pragma unroll
                for (int j = 0; j < 4; j++)
                    wmma::store_matrix_sync(&Cs[(wm + 16 * i) * LDC + (wn - 128 * h) + 16 * j],
                                            acc[i][j], LDC, wmma::mem_row_major);
        }
        __syncthreads();

        const int c4 = lane * 4;
        const float4 bb = *(const float4*)&bv[h * 128 + c4];
        float4 colsum = make_float4(0.f, 0.f, 0.f, 0.f);
#pragma unroll
        for (int i = 0; i < 8; i++) {
            const int r = wid + 8 * i;
            float4 v = *(float4*)&Cs[r * LDC + c4];
            float4 o;
            o.x = sigmoid_fast(v.x + bb.x);
            o.y = sigmoid_fast(v.y + bb.y);
            o.z = sigmoid_fast(v.z + bb.z);
            o.w = sigmoid_fast(v.w + bb.w);
            const size_t goff = (size_t)(m0 + r) * D_ + h * 128 + c4;
            *(__nv_bfloat162*)&C[goff]     = __floats2bfloat162_rn(o.x, o.y);
            *(__nv_bfloat162*)&C[goff + 2] = __floats2bfloat162_rn(o.z, o.w);
            if (is_k) {
                colsum.x += o.x; colsum.y += o.y; colsum.z += o.z; colsum.w += o.w;
            } else {
                float rs = o.x + o.y + o.z + o.w;
#pragma unroll
                for (int off = 16; off; off >>= 1)
                    rs += __shfl_xor_sync(0xffffffffu, rs, off);
                if (lane == 0)
                    g_rowp[(size_t)(m0 + r) * 2 + h] = rs;
            }
        }
        __syncthreads();
        if (is_k) {
            float* cred = Cs;                       // reuse (8 warps x 128 cols)
            *(float4*)&cred[wid * 128 + c4] = colsum;
            __syncthreads();
            if (tid < 32) {
                float4 s = make_float4(0.f, 0.f, 0.f, 0.f);
#pragma unroll
                for (int w = 0; w < 8; w++) {
                    float4 v = *(float4*)&cred[w * 128 + tid * 4];
                    s.x += v.x; s.y += v.y; s.z += v.z; s.w += v.w;
                }
                *(float4*)&g_colp[(size_t)blockIdx.x * D_ + h * 128 + tid * 4] = s;
            }
            __syncthreads();
        }
    }
}

// ============================================================================
// Kernel 2: single-pass column softmax (bounded x, no max subtraction).
// colsum from 64 row-block partials. Writes unnormalized exp (bf16) + colinv.
// grid (B, D/32), 1024 threads: 16 d-pair lanes x 64 n-lanes.
// ============================================================================
__global__ __launch_bounds__(1024, 1)
void col_softmax_kernel(const float* __restrict__ V)
{
    const int b   = blockIdx.x;
    const int td  = threadIdx.x & 15;          // d-pair lane
    const int tn  = threadIdx.x >> 4;          // 0..63
    const int d0  = blockIdx.y * 32 + 2 * td;

    __shared__ float2 red[64][17];

    // colsum for this block's 32 d's from 64 row-block partials
    float2 cs = *(const float2*)&g_colp[(size_t)(b * 64 + tn) * D_ + d0];
    red[tn][td] = cs;
    __syncthreads();
#pragma unroll
    for (int h = 32; h; h >>= 1) {
        if (tn < h) {
            red[tn][td].x += red[tn + h][td].x;
            red[tn][td].y += red[tn + h][td].y;
        }
        __syncthreads();
    }
    const float cx = __fdividef(1.f, red[0][td].x + EPS_);
    const float cy = __fdividef(1.f, red[0][td].y + EPS_);
    __syncthreads();

    const __nv_bfloat16* Pk = g_phi_k + (size_t)b * N_ * D_ + d0;
    const float*         Vv = V       + (size_t)b * N_ * D_ + d0;
    __nv_bfloat16*       Ex = g_Ex    + (size_t)b * N_ * D_ + d0;

    float2 se = make_float2(0.f, 0.f);
    for (int n = tn; n < N_; n += 64) {
        const size_t off = (size_t)n * D_;
        __nv_bfloat162 pk2 = *(const __nv_bfloat162*)(Pk + off);
        float2 v2 = *(const float2*)(Vv + off);
        float ex = __expf(cx * __bfloat162float(pk2.x) * v2.x);
        float ey = __expf(cy * __bfloat162float(pk2.y) * v2.y);
        *(__nv_bfloat162*)(Ex + off) = __floats2bfloat162_rn(ex, ey);
        se.x += ex; se.y += ey;
    }
    red[tn][td] = se;
    __syncthreads();
#pragma unroll
    for (int h = 32; h; h >>= 1) {
        if (tn < h) {
            red[tn][td].x += red[tn + h][td].x;
            red[tn][td].y += red[tn + h][td].y;
        }
        __syncthreads();
    }
    if (tn == 0) {
        g_colinv[b * D_ + d0]     = __fdividef(1.f, red[0][td].x);
        g_colinv[b * D_ + d0 + 1] = __fdividef(1.f, red[0][td].y);
    }
}

// ============================================================================
// Kernel 3: KV partials = phi_k^T @ Ex per batch, split-K over N.
// 128x128x32, 8 warps (4m x 2n), both operands cp.async double-buffered.
// ============================================================================
__global__ __launch_bounds__(256, 2)
void kv_gemm_bf16()
{
    const int b  = blockIdx.z / SPLITK;
    const int s  = blockIdx.z % SPLITK;
    const int d0 = blockIdx.x * 128;
    const int e0 = blockIdx.y * 128;

    const __nv_bfloat16* Pk = g_phi_k + (size_t)b * N_ * D_;
    const __nv_bfloat16* Ex = g_Ex    + (size_t)b * N_ * D_;
    float* Cout = g_KVp + ((size_t)s * B_ + b) * D_ * D_;

    __shared__ __align__(16) __nv_bfloat16 As2[2][32 * LDKV];
    __shared__ __align__(16) __nv_bfloat16 Bs2[2][32 * LDKV];

    const int tid = threadIdx.x;
    const int wid = tid >> 5;
    const int wm = (wid & 3) * 32;
    const int wn = (wid >> 2) * 64;

    HC acc[2][4];
#pragma unroll
    for (int i = 0; i < 2; i++)
#pragma unroll
        for (int j = 0; j < 4; j++) wmma::fill_fragment(acc[i][j], 0.f);

    const int nbeg = s * (N_ / SPLITK);
    constexpr int ITERS = (N_ / SPLITK) / 32;   // 16

    auto load_tile = [&](int it, int bb) {
        const int n0 = nbeg + it * 32;
#pragma unroll
        for (int j = 0; j < 2; j++) {
            const int f = tid + 256 * j;        // 512 chunks per operand
            const int r = f >> 4, c8 = (f & 15) * 8;
            cp_async16(&As2[bb][r * LDKV + c8], &Pk[(size_t)(n0 + r) * D_ + d0 + c8]);
            cp_async16(&Bs2[bb][r * LDKV + c8], &Ex[(size_t)(n0 + r) * D_ + e0 + c8]);
        }
        cp_commit();
    };

    load_tile(0, 0);
    for (int it = 0; it < ITERS; it++) {
        if (it + 1 < ITERS) { load_tile(it + 1, (it + 1) & 1); cp_wait1(); }
        else                { cp_wait0(); }
        __syncthreads();
        const __nv_bfloat16* Ab = As2[it & 1];
        const __nv_bfloat16* Bb = Bs2[it & 1];
#pragma unroll
        for (int kk = 0; kk < 32; kk += 16) {
            HAc a[2]; HB b2[4];
#pragma unroll
            for (int i = 0; i < 2; i++)
                wmma::load_matrix_sync(a[i], &Ab[kk * LDKV + wm + 16 * i], LDKV);
#pragma unroll
            for (int j = 0; j < 4; j++)
                wmma::load_matrix_sync(b2[j], &Bb[kk * LDKV + wn + 16 * j], LDKV);
#pragma unroll
            for (int i = 0; i < 2; i++)
#pragma unroll
                for (int j = 0; j < 4; j++)
                    wmma::mma_sync(acc[i][j], a[i], b2[j], acc[i][j]);
        }
        __syncthreads();
    }

#pragma unroll
    for (int i = 0; i < 2; i++)
#pragma unroll
        for (int j = 0; j < 4; j++)
            wmma::store_matrix_sync(&Cout[(size_t)(d0 + wm + 16 * i) * D_ + e0 + wn + 16 * j],
                                    acc[i][j], D_, wmma::mem_row_major);
}

// Deterministic split-K reduce + softmax normalization -> bf16 KV
__global__ void kv_reduce_kernel()
{
    const size_t i4 = ((size_t)blockIdx.x * 256 + threadIdx.x) * 4;
    const size_t stride = (size_t)B_ * D_ * D_;
    float4 s = make_float4(0.f, 0.f, 0.f, 0.f);
#pragma unroll
    for (int p = 0; p < SPLITK; p++) {
        float4 v = *(const float4*)&g_KVp[p * stride + i4];
        s.x += v.x; s.y += v.y; s.z += v.z; s.w += v.w;
    }
    const int b = (int)(i4 / (D_ * D_));
    const int e = (int)(i4 % D_);
    float4 ci = *(const float4*)&g_colinv[b * D_ + e];
    *(__nv_bfloat162*)&g_KVh[i4]     = __floats2bfloat162_rn(s.x * ci.x, s.y * ci.y);
    *(__nv_bfloat162*)&g_KVh[i4 + 2] = __floats2bfloat162_rn(s.z * ci.z, s.w * ci.w);
}

// ============================================================================
// Kernel 4: out = (rowscale * phi_q) @ KVh. 64x256x32, rowscale folded into
// A-load; B cp.async; accumulators store straight to d_out (fp32).
// ============================================================================
__global__ __launch_bounds__(256, 2)
void out_gemm_bf16(float* __restrict__ out)
{
    const int b  = blockIdx.z;
    const int m0 = blockIdx.x * 64;   // n within batch

    const __nv_bfloat16* Aq = g_phi_q + (size_t)b * N_ * D_;
    const __nv_bfloat16* KV = g_KVh   + (size_t)b * D_ * D_;

    __shared__ __align__(16) char sm[44032];
    __nv_bfloat16* Ah[2] = { (__nv_bfloat16*)sm,
                             (__nv_bfloat16*)(sm + 5120) };
    __nv_bfloat16* Bt[2] = { (__nv_bfloat16*)(sm + 10240),
                             (__nv_bfloat16*)(sm + 10240 + 16896) };
    __shared__ float scf[64];

    const int tid = threadIdx.x;
    const int wid = tid >> 5;
    const int wm = (wid & 1) * 32;
    const int wn = (wid >> 1) * 64;

    if (tid < 64) {
        const size_t row = (size_t)b * N_ + m0 + tid;
        float rs = g_rowp[row * 2] + g_rowp[row * 2 + 1];
        scf[tid] = sigmoid_fast(rs) * __fdividef(1.f, rs + EPS_);
    }

    HC acc[2][4];
#pragma unroll
    for (int i = 0; i < 2; i++)
#pragma unroll
        for (int j = 0; j < 4; j++) wmma::fill_fragment(acc[i][j], 0.f);
    __syncthreads();

    auto load_tile = [&](int kt, int bb) {
        const int k0 = kt * 32;
        {   // A: one uint4 (8 bf16) per thread, scaled
            const int r = tid >> 2, c8 = (tid & 3) * 8;
            uint4 raw = *(const uint4*)&Aq[(size_t)(m0 + r) * D_ + k0 + c8];
            const float sc = scf[r];
            __nv_bfloat162* hp = (__nv_bfloat162*)&raw;
            uint4 ow; __nv_bfloat162* op = (__nv_bfloat162*)&ow;
#pragma unroll
            for (int t = 0; t < 4; t++) {
                float2 f2 = __bfloat1622float2(hp[t]);
                op[t] = __floats2bfloat162_rn(f2.x * sc, f2.y * sc);
            }
            *(uint4*)&Ah[bb][r * LDAH + c8] = ow;
        }
#pragma unroll
        for (int j = 0; j < 4; j++) {               // B: 1024 16B chunks
            const int f = tid + 256 * j;
            const int r = f >> 5, c8 = (f & 31) * 8;
            cp_async16(&Bt[bb][r * LDW + c8], &KV[(size_t)(k0 + r) * D_ + c8]);
        }
        cp_commit();
    };

    load_tile(0, 0);
    for (int kt = 0; kt < 8; kt++) {
        if (kt < 7) { load_tile(kt + 1, (kt + 1) & 1); cp_wait1(); }
        else        { cp_wait0(); }
        __syncthreads();
        const __nv_bfloat16* Ab = Ah[kt & 1];
        const __nv_bfloat16* Bb = Bt[kt & 1];
#pragma unroll
        for (int kk = 0; kk < 32; kk += 16) {
            HA a[2]; HB b2[4];
#pragma unroll
            for (int i = 0; i < 2; i++)
                wmma::load_matrix_sync(a[i], &Ab[(wm + 16 * i) * LDAH + kk], LDAH);
#pragma unroll
            for (int j = 0; j < 4; j++)
                wmma::load_matrix_sync(b2[j], &Bb[kk * LDW + wn + 16 * j], LDW);
#pragma unroll
            for (int i = 0; i < 2; i++)
#pragma unroll
                for (int j = 0; j < 4; j++)
                    wmma::mma_sync(acc[i][j], a[i], b2[j], acc[i][j]);
        }
        __syncthreads();
    }

#pragma unroll
    for (int i = 0; i < 2; i++)
#pragma unroll
        for (int j = 0; j < 4; j++)
            wmma::store_matrix_sync(&out[((size_t)b * N_ + m0 + wm + 16 * i) * D_ + wn + 16 * j],
                                    acc[i][j], D_, wmma::mem_row_major);
}

// ============================================================================
// Launch: inputs per metadata order: Q, K, V, Wq, bq, Wk, bk
// ============================================================================
extern "C" void kernel_launch(void* const* d_in, const int* in_sizes, int n_in,
                              void* d_out, int out_size)
{
    const float* Q  = (const float*)d_in[0];
    const float* K  = (const float*)d_in[1];
    const float* V  = (const float*)d_in[2];
    const float* Wq = (const float*)d_in[3];
    const float* bq = (const float*)d_in[4];
    const float* Wk = (const float*)d_in[5];
    const float* bk = (const float*)d_in[6];
    float* out = (float*)d_out;

    convert_w<<<D_ * D_ / 1024, 256>>>(Wq, Wk);
    phi_gemm_bf16<<<dim3(NMBLK, 1, 2), 256>>>(Q, K, bq, bk);
    col_softmax_kernel<<<dim3(B_, D_ / 32), 1024>>>(V);
    kv_gemm_bf16<<<dim3(2, 2, B_ * SPLITK), 256>>>();
    kv_reduce_kernel<<<(B_ * D_ * D_) / 1024, 256>>>();
    out_gemm_bf16<<<dim3(N_ / 64, 1, B_), 256>>>(out);
}